// round 3
// baseline (speedup 1.0000x reference)
#include <cuda_runtime.h>
#include <cuda_bf16.h>
#include <math.h>

#define C_CH   128
#define HW     3136          // 56*56
#define B_SZ   64
#define NCHUNK 8
#define NTOT   (B_SZ * HW)   // 200704 elements per channel
#define HW4    (HW / 4)      // 784 float4 per (b,c) plane

// scratch (no device allocation allowed)
__device__ float g_max [C_CH * NCHUNK];
__device__ float g_min [C_CH * NCHUNK];
__device__ float g_sum [C_CH * NCHUNK];

__device__ __forceinline__ float qbf(float v) {
    // bf16 round-to-nearest-even round trip == jnp astype(bf16).astype(f32)
    return __bfloat162float(__float2bfloat16(v));
}

// ---------------------------------------------------------------------------
// Pass 1: per (channel, chunk) max / min / sum over 8 batches * HW elements.
// Loop transposed so each thread front-batches 8 independent LDG.128 (MLP=8).
// max/min taken on raw fp32 (qbf is monotonic), quantized once at the end.
// ---------------------------------------------------------------------------
__global__ void __launch_bounds__(256) stats_kernel(const float* __restrict__ x) {
    const int c = blockIdx.x;    // 0..127
    const int k = blockIdx.y;    // 0..7
    const int tid = threadIdx.x;

    const float4* p[8];
    #pragma unroll
    for (int j = 0; j < 8; ++j)
        p[j] = reinterpret_cast<const float4*>(
            x + ((size_t)(8 * k + j) * C_CH + c) * HW);

    float vmax = -INFINITY, vmin = INFINITY, vsum = 0.0f;

    for (int i = tid; i < HW4; i += 256) {
        float4 v[8];
        #pragma unroll
        for (int j = 0; j < 8; ++j) v[j] = p[j][i];   // 8 independent loads

        #pragma unroll
        for (int j = 0; j < 8; ++j) {
            // raw min/max (quantize later — monotonic)
            vmax = fmaxf(vmax, fmaxf(fmaxf(v[j].x, v[j].y), fmaxf(v[j].z, v[j].w)));
            vmin = fminf(vmin, fminf(fminf(v[j].x, v[j].y), fminf(v[j].z, v[j].w)));
            // sum of quantized values
            vsum += (qbf(v[j].x) + qbf(v[j].y)) + (qbf(v[j].z) + qbf(v[j].w));
        }
    }
    vmax = qbf(vmax);
    vmin = qbf(vmin);

    // warp reduce
    #pragma unroll
    for (int o = 16; o > 0; o >>= 1) {
        vmax = fmaxf(vmax, __shfl_down_sync(0xFFFFFFFFu, vmax, o));
        vmin = fminf(vmin, __shfl_down_sync(0xFFFFFFFFu, vmin, o));
        vsum +=            __shfl_down_sync(0xFFFFFFFFu, vsum, o);
    }

    __shared__ float smax[8], smin[8], ssum[8];
    const int wid  = tid >> 5;
    const int lane = tid & 31;
    if (lane == 0) { smax[wid] = vmax; smin[wid] = vmin; ssum[wid] = vsum; }
    __syncthreads();

    if (tid == 0) {
        float m = smax[0], n = smin[0], s = ssum[0];
        #pragma unroll
        for (int w = 1; w < 8; ++w) {
            m = fmaxf(m, smax[w]);
            n = fminf(n, smin[w]);
            s += ssum[w];
        }
        g_max[c * NCHUNK + k] = m;
        g_min[c * NCHUNK + k] = n;
        g_sum[c * NCHUNK + k] = s;
    }
}

// ---------------------------------------------------------------------------
// Pass 2: out = q( q((q(x) - avg) * scale) * q(gamma) + beta )
// One block per (b,c) plane, REVERSED so the L2-resident tail of x (left there
// by the stats pass) is read first. Per-channel scalars computed redundantly
// per block (24 scalar loads) — no separate finalize kernel.
// ---------------------------------------------------------------------------
__global__ void __launch_bounds__(256) norm_kernel(const float* __restrict__ x,
                                                   const float* __restrict__ gamma,
                                                   const float* __restrict__ beta,
                                                   float* __restrict__ out) {
    const int bc = (B_SZ * C_CH - 1) - blockIdx.x;   // reversed plane order
    const int c  = bc & (C_CH - 1);

    __shared__ float s_avg, s_scale, s_g, s_be;
    if (threadIdx.x == 0) {
        float sm = 0.f, sn = 0.f, st = 0.f;
        #pragma unroll
        for (int k = 0; k < NCHUNK; ++k) {
            sm += g_max[c * NCHUNK + k];
            sn += g_min[c * NCHUNK + k];
            st += g_sum[c * NCHUNK + k];
        }
        const float sum_max = qbf(sm);
        const float sum_min = qbf(sn);
        const float avg_max = qbf(sum_max / (float)NCHUNK);
        const float avg_min = qbf(sum_min / (float)NCHUNK);
        const float total   = qbf(st);
        s_avg = qbf(total / (float)NTOT);

        const double chunk_size = (double)(NCHUNK * HW);  // 25088
        const float scale_fix = (float)(1.0 / sqrt(2.0 * log(chunk_size)));
        s_scale = qbf(1.0f / ((avg_max - avg_min) * scale_fix + 1e-5f));
        s_g  = qbf(gamma[c]);
        s_be = beta[c];
    }
    __syncthreads();

    const float avg = s_avg, scale = s_scale, g = s_g, be = s_be;

    const float4* px = reinterpret_cast<const float4*>(x)   + (size_t)bc * HW4;
    float4*       po = reinterpret_cast<float4*>(out)       + (size_t)bc * HW4;

    const int tid = threadIdx.x;
    // HW4 = 784 = 3*256 + 16: three full rounds + 16-thread tail, front-batched
    float4 v0 = px[tid];
    float4 v1 = px[tid + 256];
    float4 v2 = px[tid + 512];
    float4 v3;
    if (tid < 16) v3 = px[tid + 768];

    float4 r; float t;
    #define NORM4(V, R)                                              \
        t = qbf((qbf((V).x) - avg) * scale); (R).x = qbf(t * g + be); \
        t = qbf((qbf((V).y) - avg) * scale); (R).y = qbf(t * g + be); \
        t = qbf((qbf((V).z) - avg) * scale); (R).z = qbf(t * g + be); \
        t = qbf((qbf((V).w) - avg) * scale); (R).w = qbf(t * g + be);

    NORM4(v0, r); po[tid]       = r;
    NORM4(v1, r); po[tid + 256] = r;
    NORM4(v2, r); po[tid + 512] = r;
    if (tid < 16) { NORM4(v3, r); po[tid + 768] = r; }
    #undef NORM4
}

// ---------------------------------------------------------------------------
extern "C" void kernel_launch(void* const* d_in, const int* in_sizes, int n_in,
                              void* d_out, int out_size) {
    const float* x     = (const float*)d_in[0];
    const float* gamma = (const float*)d_in[1];
    const float* beta  = (const float*)d_in[2];
    float* out = (float*)d_out;

    dim3 grid1(C_CH, NCHUNK);
    stats_kernel<<<grid1, 256>>>(x);
    norm_kernel<<<B_SZ * C_CH, 256>>>(x, gamma, beta, out);
}

// round 4
// speedup vs baseline: 1.1364x; 1.1364x over previous
#include <cuda_runtime.h>
#include <cuda_bf16.h>
#include <math.h>

#define C_CH   128
#define HW     3136          // 56*56
#define B_SZ   64
#define NCHUNK 8
#define NTOT   (B_SZ * HW)   // 200704 elements per channel
#define HW4    (HW / 4)      // 784 float4 per (b,c) plane
#define NPLANE (B_SZ * C_CH) // 8192 planes

// scratch (no device allocation allowed)
__device__ float g_pmax[NPLANE];   // raw (unquantized) per-plane max
__device__ float g_pmin[NPLANE];
__device__ float g_psum[NPLANE];   // fp32 sum of bf16-quantized elements
__device__ float g_avg [C_CH];
__device__ float g_scale[C_CH];
__device__ float g_gam [C_CH];     // quantized gamma

__device__ __forceinline__ float qbf(float v) {
    // bf16 round-to-nearest-even round trip == jnp astype(bf16).astype(f32)
    return __bfloat162float(__float2bfloat16(v));
}

// ---------------------------------------------------------------------------
// Pass 1: one WARP per (b,c) plane — each block streams one contiguous 100KB
// region; consecutive blocks are consecutive in memory (pure linear stream).
// No atomics, no block reduction, no __syncthreads.
// ---------------------------------------------------------------------------
__global__ void __launch_bounds__(256) stats_kernel(const float* __restrict__ x) {
    const int warp = threadIdx.x >> 5;
    const int lane = threadIdx.x & 31;
    const int p    = blockIdx.x * 8 + warp;        // plane id 0..8191

    const float4* px = reinterpret_cast<const float4*>(x) + (size_t)p * HW4;

    float vmax = -INFINITY, vmin = INFINITY, vsum = 0.0f;

    // 784 = 6*128 + 16 : six unroll-4 groups (MLP=4) + 16-lane tail
    #pragma unroll
    for (int gidx = 0; gidx < 6; ++gidx) {
        const int base = gidx * 128 + lane;
        float4 v0 = px[base];
        float4 v1 = px[base + 32];
        float4 v2 = px[base + 64];
        float4 v3 = px[base + 96];
        #define ACC(V)                                                            \
            vmax = fmaxf(vmax, fmaxf(fmaxf((V).x, (V).y), fmaxf((V).z, (V).w)));  \
            vmin = fminf(vmin, fminf(fminf((V).x, (V).y), fminf((V).z, (V).w)));  \
            vsum += (qbf((V).x) + qbf((V).y)) + (qbf((V).z) + qbf((V).w));
        ACC(v0) ACC(v1) ACC(v2) ACC(v3)
        #undef ACC
    }
    if (lane < 16) {
        float4 v = px[768 + lane];
        vmax = fmaxf(vmax, fmaxf(fmaxf(v.x, v.y), fmaxf(v.z, v.w)));
        vmin = fminf(vmin, fminf(fminf(v.x, v.y), fminf(v.z, v.w)));
        vsum += (qbf(v.x) + qbf(v.y)) + (qbf(v.z) + qbf(v.w));
    }

    // warp reduce
    #pragma unroll
    for (int o = 16; o > 0; o >>= 1) {
        vmax = fmaxf(vmax, __shfl_down_sync(0xFFFFFFFFu, vmax, o));
        vmin = fminf(vmin, __shfl_down_sync(0xFFFFFFFFu, vmin, o));
        vsum +=            __shfl_down_sync(0xFFFFFFFFu, vsum, o);
    }
    if (lane == 0) {
        g_pmax[p] = vmax;   // raw; quantized once after chunk-max (monotonic)
        g_pmin[p] = vmin;
        g_psum[p] = vsum;
    }
}

// ---------------------------------------------------------------------------
// Pass 2: per-channel scalars (1 block, 128 threads). Coalesced loads:
// for fixed (k,b'), c varies across threads -> consecutive addresses.
// ---------------------------------------------------------------------------
__global__ void finalize_kernel(const float* __restrict__ gamma) {
    const int c = threadIdx.x;

    float sm = 0.f, sn = 0.f, st = 0.f;
    #pragma unroll
    for (int k = 0; k < NCHUNK; ++k) {
        float cmax = -INFINITY, cmin = INFINITY, cs = 0.f;
        #pragma unroll
        for (int b = 0; b < 8; ++b) {
            const int p = (8 * k + b) * C_CH + c;
            cmax = fmaxf(cmax, g_pmax[p]);
            cmin = fminf(cmin, g_pmin[p]);
            cs  += g_psum[p];
        }
        sm += qbf(cmax);   // chunk max of quantized elems == q(raw chunk max)
        sn += qbf(cmin);
        st += cs;
    }
    const float sum_max = qbf(sm);
    const float sum_min = qbf(sn);
    const float avg_max = qbf(sum_max / (float)NCHUNK);
    const float avg_min = qbf(sum_min / (float)NCHUNK);
    const float total   = qbf(st);

    const double chunk_size = (double)(NCHUNK * HW);  // 25088
    const float scale_fix = (float)(1.0 / sqrt(2.0 * log(chunk_size)));

    g_avg[c]   = qbf(total / (float)NTOT);
    g_scale[c] = qbf(1.0f / ((avg_max - avg_min) * scale_fix + 1e-5f));
    g_gam[c]   = qbf(gamma[c]);
}

// ---------------------------------------------------------------------------
// Pass 3: out = q( q((q(x) - avg) * scale) * q(gamma) + beta )
// One block per plane; 3 front-batched float4 + 16-thread tail.
// Streaming stores (__stcs) to keep output from churning L2.
// ---------------------------------------------------------------------------
__global__ void __launch_bounds__(256) norm_kernel(const float* __restrict__ x,
                                                   const float* __restrict__ beta,
                                                   float* __restrict__ out) {
    const int bc = blockIdx.x;
    const int c  = bc & (C_CH - 1);

    const float avg   = g_avg[c];
    const float scale = g_scale[c];
    const float g     = g_gam[c];
    const float be    = beta[c];

    const float4* px = reinterpret_cast<const float4*>(x)   + (size_t)bc * HW4;
    float4*       po = reinterpret_cast<float4*>(out)       + (size_t)bc * HW4;

    const int tid = threadIdx.x;
    float4 v0 = px[tid];
    float4 v1 = px[tid + 256];
    float4 v2 = px[tid + 512];
    float4 v3;
    if (tid < 16) v3 = px[tid + 768];

    float4 r; float t;
    #define NORM4(V, R)                                               \
        t = qbf((qbf((V).x) - avg) * scale); (R).x = qbf(t * g + be); \
        t = qbf((qbf((V).y) - avg) * scale); (R).y = qbf(t * g + be); \
        t = qbf((qbf((V).z) - avg) * scale); (R).z = qbf(t * g + be); \
        t = qbf((qbf((V).w) - avg) * scale); (R).w = qbf(t * g + be);

    NORM4(v0, r); __stcs(po + tid,       r);
    NORM4(v1, r); __stcs(po + tid + 256, r);
    NORM4(v2, r); __stcs(po + tid + 512, r);
    if (tid < 16) { NORM4(v3, r); __stcs(po + tid + 768, r); }
    #undef NORM4
}

// ---------------------------------------------------------------------------
extern "C" void kernel_launch(void* const* d_in, const int* in_sizes, int n_in,
                              void* d_out, int out_size) {
    const float* x     = (const float*)d_in[0];
    const float* gamma = (const float*)d_in[1];
    const float* beta  = (const float*)d_in[2];
    float* out = (float*)d_out;

    stats_kernel<<<NPLANE / 8, 256>>>(x);
    finalize_kernel<<<1, C_CH>>>(gamma);
    norm_kernel<<<NPLANE, 256>>>(x, beta, out);
}

// round 6
// speedup vs baseline: 1.1773x; 1.0359x over previous
#include <cuda_runtime.h>
#include <cuda_bf16.h>
#include <math.h>

#define C_CH   128
#define HW     3136          // 56*56
#define B_SZ   64
#define NCHUNK 8
#define NTOT   (B_SZ * HW)   // 200704 elements per channel
#define HW4    (HW / 4)      // 784 float4 per (b,c) plane
#define HW8    (HW / 8)      // 392 float8 (32B) per plane
#define NPLANE (B_SZ * C_CH) // 8192 planes

// scratch (no device allocation allowed)
__device__ float g_pmax[NPLANE];   // raw (unquantized) per-plane max
__device__ float g_pmin[NPLANE];
__device__ float g_psum[NPLANE];   // fp32 sum of bf16-quantized elements
__device__ float g_avg [C_CH];
__device__ float g_scale[C_CH];
__device__ float g_gam [C_CH];     // quantized gamma

__device__ __forceinline__ float qbf(float v) {
    // bf16 round-to-nearest-even round trip == jnp astype(bf16).astype(f32)
    return __bfloat162float(__float2bfloat16(v));
}

// 32-byte global load with L2 evict_last hint (sm_103 requires .v8.b32 form)
__device__ __forceinline__ void ldg_el8(const float* p, float v[8]) {
    unsigned r0, r1, r2, r3, r4, r5, r6, r7;
    asm volatile("ld.global.L2::evict_last.v8.b32 {%0,%1,%2,%3,%4,%5,%6,%7}, [%8];"
                 : "=r"(r0), "=r"(r1), "=r"(r2), "=r"(r3),
                   "=r"(r4), "=r"(r5), "=r"(r6), "=r"(r7)
                 : "l"(p));
    v[0] = __uint_as_float(r0); v[1] = __uint_as_float(r1);
    v[2] = __uint_as_float(r2); v[3] = __uint_as_float(r3);
    v[4] = __uint_as_float(r4); v[5] = __uint_as_float(r5);
    v[6] = __uint_as_float(r6); v[7] = __uint_as_float(r7);
}

// ---------------------------------------------------------------------------
// Pass 1: one WARP per (b,c) plane — pure linear stream per block.
// 256-bit loads tagged L2::evict_last so x stays resident for the norm pass
// (x = 103MB, L2 = 126MB). Plane = 392 x 32B, warp does 12 rounds + 8-lane tail.
// ---------------------------------------------------------------------------
__global__ void __launch_bounds__(256) stats_kernel(const float* __restrict__ x) {
    const int warp = threadIdx.x >> 5;
    const int lane = threadIdx.x & 31;
    const int p    = blockIdx.x * 8 + warp;        // plane id 0..8191

    const float* px = x + (size_t)p * HW;

    float vmax = -INFINITY, vmin = INFINITY, vsum = 0.0f;

    #define ACC8(V)                                                           \
        vmax = fmaxf(vmax, fmaxf(fmaxf(fmaxf((V)[0], (V)[1]), fmaxf((V)[2], (V)[3])), \
                                 fmaxf(fmaxf((V)[4], (V)[5]), fmaxf((V)[6], (V)[7])))); \
        vmin = fminf(vmin, fminf(fminf(fminf((V)[0], (V)[1]), fminf((V)[2], (V)[3])), \
                                 fminf(fminf((V)[4], (V)[5]), fminf((V)[6], (V)[7])))); \
        vsum += ((qbf((V)[0]) + qbf((V)[1])) + (qbf((V)[2]) + qbf((V)[3])))   \
              + ((qbf((V)[4]) + qbf((V)[5])) + (qbf((V)[6]) + qbf((V)[7])));

    // 392 = 3*(4*32) + 8 : three unroll-4 groups (MLP=4, 32B each) + tail
    #pragma unroll
    for (int gidx = 0; gidx < 3; ++gidx) {
        const int base = (gidx * 128 + lane) * 8;
        float v0[8], v1[8], v2[8], v3[8];
        ldg_el8(px + base,            v0);
        ldg_el8(px + base + 32 * 8,   v1);
        ldg_el8(px + base + 64 * 8,   v2);
        ldg_el8(px + base + 96 * 8,   v3);
        ACC8(v0) ACC8(v1) ACC8(v2) ACC8(v3)
    }
    if (lane < 8) {
        float v[8];
        ldg_el8(px + (384 + lane) * 8, v);
        ACC8(v)
    }
    #undef ACC8

    // warp reduce
    #pragma unroll
    for (int o = 16; o > 0; o >>= 1) {
        vmax = fmaxf(vmax, __shfl_down_sync(0xFFFFFFFFu, vmax, o));
        vmin = fminf(vmin, __shfl_down_sync(0xFFFFFFFFu, vmin, o));
        vsum +=            __shfl_down_sync(0xFFFFFFFFu, vsum, o);
    }
    if (lane == 0) {
        g_pmax[p] = vmax;   // raw; quantized after chunk-max (monotonic)
        g_pmin[p] = vmin;
        g_psum[p] = vsum;
    }
}

// ---------------------------------------------------------------------------
// Pass 2: per-channel scalars (1 block, 128 threads).
// ---------------------------------------------------------------------------
__global__ void finalize_kernel(const float* __restrict__ gamma) {
    const int c = threadIdx.x;

    float sm = 0.f, sn = 0.f, st = 0.f;
    #pragma unroll
    for (int k = 0; k < NCHUNK; ++k) {
        float cmax = -INFINITY, cmin = INFINITY, cs = 0.f;
        #pragma unroll
        for (int b = 0; b < 8; ++b) {
            const int p = (8 * k + b) * C_CH + c;
            cmax = fmaxf(cmax, g_pmax[p]);
            cmin = fminf(cmin, g_pmin[p]);
            cs  += g_psum[p];
        }
        sm += qbf(cmax);   // chunk-max of quantized elems == q(raw chunk max)
        sn += qbf(cmin);
        st += cs;
    }
    const float sum_max = qbf(sm);
    const float sum_min = qbf(sn);
    const float avg_max = qbf(sum_max / (float)NCHUNK);
    const float avg_min = qbf(sum_min / (float)NCHUNK);
    const float total   = qbf(st);

    const double chunk_size = (double)(NCHUNK * HW);  // 25088
    const float scale_fix = (float)(1.0 / sqrt(2.0 * log(chunk_size)));

    g_avg[c]   = qbf(total / (float)NTOT);
    g_scale[c] = qbf(1.0f / ((avg_max - avg_min) * scale_fix + 1e-5f));
    g_gam[c]   = qbf(gamma[c]);
}

// ---------------------------------------------------------------------------
// Pass 3: out = q( q((q(x) - avg) * scale) * q(gamma) + beta )
// Reads via __ldcs (one-time re-read; demote the pinned line after use),
// writes via __stcs (don't let output churn L2).
// ---------------------------------------------------------------------------
__global__ void __launch_bounds__(256) norm_kernel(const float* __restrict__ x,
                                                   const float* __restrict__ beta,
                                                   float* __restrict__ out) {
    const int bc = blockIdx.x;
    const int c  = bc & (C_CH - 1);

    const float avg   = g_avg[c];
    const float scale = g_scale[c];
    const float g     = g_gam[c];
    const float be    = beta[c];

    const float4* px = reinterpret_cast<const float4*>(x)   + (size_t)bc * HW4;
    float4*       po = reinterpret_cast<float4*>(out)       + (size_t)bc * HW4;

    const int tid = threadIdx.x;
    float4 v0 = __ldcs(px + tid);
    float4 v1 = __ldcs(px + tid + 256);
    float4 v2 = __ldcs(px + tid + 512);
    float4 v3;
    if (tid < 16) v3 = __ldcs(px + tid + 768);

    float4 r; float t;
    #define NORM4(V, R)                                               \
        t = qbf((qbf((V).x) - avg) * scale); (R).x = qbf(t * g + be); \
        t = qbf((qbf((V).y) - avg) * scale); (R).y = qbf(t * g + be); \
        t = qbf((qbf((V).z) - avg) * scale); (R).z = qbf(t * g + be); \
        t = qbf((qbf((V).w) - avg) * scale); (R).w = qbf(t * g + be);

    NORM4(v0, r); __stcs(po + tid,       r);
    NORM4(v1, r); __stcs(po + tid + 256, r);
    NORM4(v2, r); __stcs(po + tid + 512, r);
    if (tid < 16) { NORM4(v3, r); __stcs(po + tid + 768, r); }
    #undef NORM4
}

// ---------------------------------------------------------------------------
extern "C" void kernel_launch(void* const* d_in, const int* in_sizes, int n_in,
                              void* d_out, int out_size) {
    const float* x     = (const float*)d_in[0];
    const float* gamma = (const float*)d_in[1];
    const float* beta  = (const float*)d_in[2];
    float* out = (float*)d_out;

    stats_kernel<<<NPLANE / 8, 256>>>(x);
    finalize_kernel<<<1, C_CH>>>(gamma);
    norm_kernel<<<NPLANE, 256>>>(x, beta, out);
}